// round 6
// baseline (speedup 1.0000x reference)
#include <cuda_runtime.h>
#include <math.h>

// Problem constants
#define NVOX 32768          // 32*32*32 voxels
#define NC   64             // channels
#define DP2  36             // padded dim + extra zero ring
#define GC   32             // channels per group
#define NG   2              // groups
#define NP   27             // kernel points
#define NOFF 162            // G*P*3
#define NMSK 54             // G*P
#define NJP  320            // padded j rows: 64 inp | 162 off | 54 mask | 40 zero
#define VOLG2 (DP2*DP2*DP2*GC)   // per-group ring-padded volume floats
#define PADVOL2 (NG*VOLG2)
#define KDW_BLOCKS 2048     // k_dw grid (32 x 64)

// ---- scratch (static device globals; zero-initialized at module load) ----
__device__ __align__(256) float g_xc[NC*NVOX];     // depthwise conv out, c-major [c][v]
__device__ __align__(256) float g_xpad2[PADVOL2];  // ring-padded projected volume
                                                   // [g][z'][y'][x'][gc]; rings stay 0
__device__ __align__(256) float g_off[NOFF*NVOX];  // offsets, transposed [j][v]
__device__ __align__(256) float g_mask[NMSK*NVOX]; // mask logits, transposed [j][v]
__device__ float g_part[KDW_BLOCKS*2];             // per-block (sum, sumsq)
__device__ float g_stats[2];                       // mean, rstd
__device__ __align__(256) float g_wtT[NC*NJP];     // weights [k][j], j-reordered+padded
__device__ float g_bias[NJP];                      // reordered bias

// ---------------------------------------------------------------------------
// Kernel 0: build reordered weight matrix [k][j] + bias
// ---------------------------------------------------------------------------
__global__ void k_init(const float* __restrict__ inp_w, const float* __restrict__ off_w,
                       const float* __restrict__ mask_w,
                       const float* __restrict__ inp_b, const float* __restrict__ off_b,
                       const float* __restrict__ mask_b) {
    int gid = blockIdx.x * 256 + threadIdx.x;
    if (gid < NC * NJP) {
        int k = gid / NJP, j = gid - k * NJP;
        float v = 0.f;
        if (j < 64)       v = inp_w[k * NC + j];
        else if (j < 226) v = off_w[k * NOFF + (j - 64)];
        else if (j < 280) v = mask_w[k * NMSK + (j - 226)];
        g_wtT[gid] = v;
    }
    if (gid < NJP) {
        int j = gid;
        float b = 0.f;
        if (j < 64)       b = inp_b[j];
        else if (j < 226) b = off_b[j - 64];
        else if (j < 280) b = mask_b[j - 226];
        g_bias[j] = b;
    }
}

// ---------------------------------------------------------------------------
// Kernel 1: depthwise 3x3x3 conv via smem slab (3 z-slices + halo).
// grid (32, 64): blockIdx.x = z slice, blockIdx.y = channel. 256 threads.
// ---------------------------------------------------------------------------
__global__ void k_dw(const float* __restrict__ x, const float* __restrict__ dw_w) {
    int bz = blockIdx.x, c = blockIdx.y;
    int tid = threadIdx.x;
    __shared__ float s[3][34][34];
    __shared__ float sh[8][2];

    const float* xs = x + c * NVOX;
    for (int i = tid; i < 3 * 34 * 34; i += 256) {
        int sl = i / 1156;
        int rem = i - sl * 1156;
        int yy = rem / 34;
        int xx = rem - yy * 34;
        int z = bz + sl - 1, y = yy - 1, xg = xx - 1;
        float val = 0.f;
        if ((unsigned)z < 32u && (unsigned)y < 32u && (unsigned)xg < 32u)
            val = xs[(z << 10) + (y << 5) + xg];
        s[sl][yy][xx] = val;
    }
    float w[27];
#pragma unroll
    for (int k = 0; k < 27; k++) w[k] = __ldg(dw_w + c * 27 + k);
    __syncthreads();

    float ls = 0.f, ls2 = 0.f;
#pragma unroll
    for (int q = 0; q < 4; q++) {
        int vloc = q * 256 + tid;
        int iy = vloc >> 5, ix = vloc & 31;
        float acc = 0.f;
#pragma unroll
        for (int kz = 0; kz < 3; kz++)
#pragma unroll
            for (int ky = 0; ky < 3; ky++)
#pragma unroll
                for (int kx = 0; kx < 3; kx++)
                    acc = fmaf(w[kz*9 + ky*3 + kx], s[kz][iy + ky][ix + kx], acc);
        g_xc[c * NVOX + (bz << 10) + vloc] = acc;
        ls += acc; ls2 += acc * acc;
    }

#pragma unroll
    for (int o = 16; o > 0; o >>= 1) {
        ls  += __shfl_down_sync(0xffffffffu, ls,  o);
        ls2 += __shfl_down_sync(0xffffffffu, ls2, o);
    }
    int lane = tid & 31, warp = tid >> 5;
    if (lane == 0) { sh[warp][0] = ls; sh[warp][1] = ls2; }
    __syncthreads();
    if (tid == 0) {
        float S = 0.f, S2 = 0.f;
#pragma unroll
        for (int i = 0; i < 8; i++) { S += sh[i][0]; S2 += sh[i][1]; }
        int bid = c * 32 + bz;
        g_part[bid * 2]     = S;
        g_part[bid * 2 + 1] = S2;
    }
}

// ---------------------------------------------------------------------------
// Kernel 2: finalize mean / rstd (1024 threads)
// ---------------------------------------------------------------------------
__global__ void k_stats() {
    int tid = threadIdx.x;
    float s = 0.f, s2 = 0.f;
    for (int i = tid; i < KDW_BLOCKS; i += 1024) {
        float2 p = reinterpret_cast<const float2*>(g_part)[i];
        s += p.x; s2 += p.y;
    }
#pragma unroll
    for (int o = 16; o > 0; o >>= 1) {
        s  += __shfl_down_sync(0xffffffffu, s,  o);
        s2 += __shfl_down_sync(0xffffffffu, s2, o);
    }
    __shared__ float sh[32][2];
    int lane = tid & 31, wid = tid >> 5;
    if (lane == 0) { sh[wid][0] = s; sh[wid][1] = s2; }
    __syncthreads();
    if (tid == 0) {
        float S = 0.f, S2 = 0.f;
#pragma unroll
        for (int i = 0; i < 32; i++) { S += sh[i][0]; S2 += sh[i][1]; }
        float n   = (float)(NVOX * NC);
        float mu  = S / n;
        float var = S2 / n - mu * mu;
        g_stats[0] = mu;
        g_stats[1] = rsqrtf(var + 1e-5f);
    }
}

// ---------------------------------------------------------------------------
// Kernel 3: tiled GEMM. C[v][j] = A[v][k] * W[k][j], M=32768, N=320, K=64.
// grid (256, 5). 256 threads, thread tile 8 voxels x 4 j.
// ---------------------------------------------------------------------------
__global__ void __launch_bounds__(256)
k_point(const float* __restrict__ x,
        const float* __restrict__ gn_w, const float* __restrict__ gn_b) {
    int jt = blockIdx.y;
    int vbase = blockIdx.x * 128;
    int tid = threadIdx.x;
    __shared__ float sA[64 * 128];
    __shared__ float sB[64 * 64];

#pragma unroll
    for (int i = 0; i < 4; i++) {
        int lin = i * 1024 + tid * 4;
        int k = lin >> 6, j = lin & 63;
        *reinterpret_cast<float4*>(&sB[lin]) =
            *reinterpret_cast<const float4*>(&g_wtT[k * NJP + jt * 64 + j]);
    }
    if (jt == 0) {
#pragma unroll
        for (int i = 0; i < 8; i++) {
            int lin = i * 1024 + tid * 4;
            int k = lin >> 7, vl = lin & 127;
            *reinterpret_cast<float4*>(&sA[lin]) =
                *reinterpret_cast<const float4*>(&x[k * NVOX + vbase + vl]);
        }
    } else {
        float mu = g_stats[0], rstd = g_stats[1];
#pragma unroll
        for (int i = 0; i < 8; i++) {
            int lin = i * 1024 + tid * 4;
            int k = lin >> 7, vl = lin & 127;
            float gw = __ldg(gn_w + k) * rstd;
            float gb = __ldg(gn_b + k) - mu * gw;
            float4 xv = *reinterpret_cast<const float4*>(&g_xc[k * NVOX + vbase + vl]);
            float r[4] = {xv.x, xv.y, xv.z, xv.w};
#pragma unroll
            for (int e = 0; e < 4; e++) {
                float xn = r[e] * gw + gb;
                float u = xn + 0.044715f * xn * xn * xn;
                r[e] = xn / (1.f + __expf(-1.5957691216057308f * u));
            }
            *reinterpret_cast<float4*>(&sA[lin]) = make_float4(r[0], r[1], r[2], r[3]);
        }
    }
    __syncthreads();

    int tx = tid & 15, ty = tid >> 4;
    float acc[8][4];
#pragma unroll
    for (int i = 0; i < 8; i++)
#pragma unroll
        for (int j = 0; j < 4; j++) acc[i][j] = 0.f;

    const float4* A4 = reinterpret_cast<const float4*>(sA);
    const float4* B4 = reinterpret_cast<const float4*>(sB);
#pragma unroll 8
    for (int k = 0; k < 64; k++) {
        float4 a0 = A4[k * 32 + tx];
        float4 a1 = A4[k * 32 + 16 + tx];
        float4 b  = B4[k * 16 + ty];
        float av[8] = {a0.x, a0.y, a0.z, a0.w, a1.x, a1.y, a1.z, a1.w};
        float bv[4] = {b.x, b.y, b.z, b.w};
#pragma unroll
        for (int i = 0; i < 8; i++)
#pragma unroll
            for (int j = 0; j < 4; j++)
                acc[i][j] = fmaf(av[i], bv[j], acc[i][j]);
    }

    if (jt == 0) {
        int o = ty * 4;
        int g = o >> 5, ch = o & 31;
        float4 b4 = *reinterpret_cast<const float4*>(&g_bias[o]);
#pragma unroll
        for (int vi = 0; vi < 8; vi++) {
            int v = vbase + ((vi & 4) << 4) + tx * 4 + (vi & 3);
            int iz = v >> 10, iy = (v >> 5) & 31, ix = v & 31;
            // ring-padded volume: interior starts at +2
            int idx = ((((g * DP2 + iz + 2) * DP2 + iy + 2) * DP2 + ix + 2) << 5) + ch;
            *reinterpret_cast<float4*>(&g_xpad2[idx]) =
                make_float4(acc[vi][0] + b4.x, acc[vi][1] + b4.y,
                            acc[vi][2] + b4.z, acc[vi][3] + b4.w);
        }
    } else {
#pragma unroll
        for (int jj = 0; jj < 4; jj++) {
            int j = jt * 64 + ty * 4 + jj;
            float* dst;
            if (j < 226)      dst = g_off  + (j - 64)  * NVOX;
            else if (j < 280) dst = g_mask + (j - 226) * NVOX;
            else continue;
            float bj = g_bias[j];
            *reinterpret_cast<float4*>(dst + vbase + tx * 4) =
                make_float4(acc[0][jj] + bj, acc[1][jj] + bj,
                            acc[2][jj] + bj, acc[3][jj] + bj);
            *reinterpret_cast<float4*>(dst + vbase + 64 + tx * 4) =
                make_float4(acc[4][jj] + bj, acc[5][jj] + bj,
                            acc[6][jj] + bj, acc[7][jj] + bj);
        }
    }
}

// ---------------------------------------------------------------------------
// Kernel 4: deformable trilinear sampling + masked accumulate + output GEMM.
// Branchless: clamp corners into [0,35]; zero ring makes OOB contribute 0.
// 8 tap loads issued back-to-back (MLP=8) before any weighting.
// ---------------------------------------------------------------------------
__global__ void k_sample(const float* __restrict__ out_w, const float* __restrict__ out_b,
                         float* __restrict__ out) {
    int v0 = blockIdx.x * 16;
    int tid = threadIdx.x;
    __shared__ float s_off[16][NOFF];
    __shared__ float s_m[16][NMSK];
    __shared__ float s_acc[16][NC];

    for (int idx = tid; idx < 16 * NOFF; idx += 256) {
        int j = idx >> 4, vloc = idx & 15;
        s_off[vloc][j] = g_off[j * NVOX + v0 + vloc];
    }
    for (int idx = tid; idx < 16 * NMSK; idx += 256) {
        int j = idx >> 4, vloc = idx & 15;
        s_m[vloc][j] = g_mask[j * NVOX + v0 + vloc];
    }
    __syncthreads();

    if (tid < 32) {
        int vv = tid >> 1, gi = tid & 1;
        float* m = &s_m[vv][gi * NP];
        float mx = -1e30f;
#pragma unroll
        for (int p = 0; p < NP; p++) mx = fmaxf(mx, m[p]);
        float s = 0.f;
#pragma unroll
        for (int p = 0; p < NP; p++) { float e = __expf(m[p] - mx); m[p] = e; s += e; }
        float inv = 1.f / s;
#pragma unroll
        for (int p = 0; p < NP; p++) m[p] *= inv;
    }
    __syncthreads();

    int vv = tid >> 4;
    int gi = (tid >> 3) & 1;
    int c4 = tid & 7;
    int v = v0 + vv;
    int iz = v >> 10, iy = (v >> 5) & 31, ix = v & 31;

    const float4* vol = reinterpret_cast<const float4*>(g_xpad2) + gi * (VOLG2 / 4) + c4;
    const float* offp = &s_off[vv][gi * (NP * 3)];
    const float* mp   = &s_m[vv][gi * NP];

    float4 acc = make_float4(0.f, 0.f, 0.f, 0.f);
    int kx = 0, ky = 0, kz = 0;
#pragma unroll 1
    for (int p = 0; p < NP; p++) {
        float ox = offp[p * 3 + 0];
        float oy = offp[p * 3 + 1];
        float oz = offp[p * 3 + 2];
        // ring-padded coords: s = out_idx + k + 1 + axis_scale*0.5*off
        float sx = (float)(ix + kx + 1) + 0.25f * ox;
        float sy = (float)(iy + ky + 1) + 0.5f  * oy;
        float sz = (float)(iz + kz + 1) + 0.5f  * oz;
        if (++kx == 3) { kx = 0; if (++ky == 3) { ky = 0; ++kz; } }

        float xf = floorf(sx), yf = floorf(sy), zf = floorf(sz);
        float fx = sx - xf, fy = sy - yf, fz = sz - zf;
        int x0 = (int)xf, y0 = (int)yf, z0 = (int)zf;
        int x0c = min(max(x0, 0), DP2 - 1),     y0c = min(max(y0, 0), DP2 - 1);
        int z0c = min(max(z0, 0), DP2 - 1);
        int x1c = min(max(x0 + 1, 0), DP2 - 1), y1c = min(max(y0 + 1, 0), DP2 - 1);
        int z1c = min(max(z0 + 1, 0), DP2 - 1);

        int zy00 = (z0c * DP2 + y0c) * DP2;
        int zy01 = (z0c * DP2 + y1c) * DP2;
        int zy10 = (z1c * DP2 + y0c) * DP2;
        int zy11 = (z1c * DP2 + y1c) * DP2;

        // 8 independent tap loads (MLP=8)
        float4 t000 = vol[(zy00 + x0c) << 3];
        float4 t001 = vol[(zy00 + x1c) << 3];
        float4 t010 = vol[(zy01 + x0c) << 3];
        float4 t011 = vol[(zy01 + x1c) << 3];
        float4 t100 = vol[(zy10 + x0c) << 3];
        float4 t101 = vol[(zy10 + x1c) << 3];
        float4 t110 = vol[(zy11 + x0c) << 3];
        float4 t111 = vol[(zy11 + x1c) << 3];

        float gx1 = fx, gx0 = 1.f - fx;
        float gy1 = fy, gy0 = 1.f - fy;
        float gz1 = fz, gz0 = 1.f - fz;
        float w00 = gz0 * gy0, w01 = gz0 * gy1, w10 = gz1 * gy0, w11 = gz1 * gy1;
        float w000 = w00 * gx0, w001 = w00 * gx1;
        float w010 = w01 * gx0, w011 = w01 * gx1;
        float w100 = w10 * gx0, w101 = w10 * gx1;
        float w110 = w11 * gx0, w111 = w11 * gx1;

        float4 smp;
        smp.x = w000 * t000.x; smp.y = w000 * t000.y;
        smp.z = w000 * t000.z; smp.w = w000 * t000.w;
        smp.x = fmaf(w001, t001.x, smp.x); smp.y = fmaf(w001, t001.y, smp.y);
        smp.z = fmaf(w001, t001.z, smp.z); smp.w = fmaf(w001, t001.w, smp.w);
        smp.x = fmaf(w010, t010.x, smp.x); smp.y = fmaf(w010, t010.y, smp.y);
        smp.z = fmaf(w010, t010.z, smp.z); smp.w = fmaf(w010, t010.w, smp.w);
        smp.x = fmaf(w011, t011.x, smp.x); smp.y = fmaf(w011, t011.y, smp.y);
        smp.z = fmaf(w011, t011.z, smp.z); smp.w = fmaf(w011, t011.w, smp.w);
        smp.x = fmaf(w100, t100.x, smp.x); smp.y = fmaf(w100, t100.y, smp.y);
        smp.z = fmaf(w100, t100.z, smp.z); smp.w = fmaf(w100, t100.w, smp.w);
        smp.x = fmaf(w101, t101.x, smp.x); smp.y = fmaf(w101, t101.y, smp.y);
        smp.z = fmaf(w101, t101.z, smp.z); smp.w = fmaf(w101, t101.w, smp.w);
        smp.x = fmaf(w110, t110.x, smp.x); smp.y = fmaf(w110, t110.y, smp.y);
        smp.z = fmaf(w110, t110.z, smp.z); smp.w = fmaf(w110, t110.w, smp.w);
        smp.x = fmaf(w111, t111.x, smp.x); smp.y = fmaf(w111, t111.y, smp.y);
        smp.z = fmaf(w111, t111.z, smp.z); smp.w = fmaf(w111, t111.w, smp.w);

        float m = mp[p];
        acc.x = fmaf(m, smp.x, acc.x);
        acc.y = fmaf(m, smp.y, acc.y);
        acc.z = fmaf(m, smp.z, acc.z);
        acc.w = fmaf(m, smp.w, acc.w);
    }

    int ch = gi * GC + c4 * 4;
    s_acc[vv][ch + 0] = acc.x;
    s_acc[vv][ch + 1] = acc.y;
    s_acc[vv][ch + 2] = acc.z;
    s_acc[vv][ch + 3] = acc.w;
    __syncthreads();

    int vq = tid >> 6;
    int oc = tid & 63;
    float b = __ldg(out_b + oc);
    float o0 = b, o1 = b, o2 = b, o3 = b;
#pragma unroll 8
    for (int c = 0; c < NC; c++) {
        float w = __ldg(out_w + c * NC + oc);
        o0 = fmaf(s_acc[vq * 4 + 0][c], w, o0);
        o1 = fmaf(s_acc[vq * 4 + 1][c], w, o1);
        o2 = fmaf(s_acc[vq * 4 + 2][c], w, o2);
        o3 = fmaf(s_acc[vq * 4 + 3][c], w, o3);
    }
    out[(v0 + vq * 4 + 0) * NC + oc] = o0;
    out[(v0 + vq * 4 + 1) * NC + oc] = o1;
    out[(v0 + vq * 4 + 2) * NC + oc] = o2;
    out[(v0 + vq * 4 + 3) * NC + oc] = o3;
}

// ---------------------------------------------------------------------------
extern "C" void kernel_launch(void* const* d_in, const int* in_sizes, int n_in,
                              void* d_out, int out_size) {
    const float* x      = (const float*)d_in[0];
    const float* dw_w   = (const float*)d_in[1];
    const float* gn_w   = (const float*)d_in[2];
    const float* gn_b   = (const float*)d_in[3];
    const float* inp_w  = (const float*)d_in[4];
    const float* inp_b  = (const float*)d_in[5];
    const float* off_w  = (const float*)d_in[6];
    const float* off_b  = (const float*)d_in[7];
    const float* mask_w = (const float*)d_in[8];
    const float* mask_b = (const float*)d_in[9];
    const float* out_w  = (const float*)d_in[10];
    const float* out_b  = (const float*)d_in[11];
    float* out = (float*)d_out;

    k_init<<<(NC * NJP + 255) / 256, 256>>>(inp_w, off_w, mask_w, inp_b, off_b, mask_b);
    k_dw<<<dim3(32, 64), 256>>>(x, dw_w);
    k_stats<<<1, 1024>>>();
    k_point<<<dim3(NVOX / 128, 5), 256>>>(x, gn_w, gn_b);
    k_sample<<<NVOX / 16, 256>>>(out_w, out_b, out);
}

// round 9
// speedup vs baseline: 1.2882x; 1.2882x over previous
#include <cuda_runtime.h>
#include <cuda_fp16.h>
#include <math.h>

// Problem constants
#define NVOX 32768          // 32*32*32 voxels
#define NC   64             // channels
#define DP2  36             // padded dim + extra zero ring
#define GC   32             // channels per group
#define NG   2              // groups
#define NP   27             // kernel points
#define NOFF 162            // G*P*3
#define NMSK 54             // G*P
#define NJP  320            // padded j rows: 64 inp | 162 off | 54 mask | 40 zero
#define HVOL  (DP2*DP2*DP2*GC)  // halves per group = 1492992
#define HVOL4 (HVOL/8)          // float4 (8 halves) per group = 186624
#define KDW_BLOCKS 2048

// ---- scratch (static device globals; zero-initialized at module load) ----
__device__ __align__(256) float  g_xc[NC*NVOX];     // depthwise conv out, c-major [c][v]
__device__ __align__(256) __half g_xph[NG*HVOL];    // fp16 ring-padded projected volume
                                                    // [g][z'][y'][x'][32ch]; rings stay 0
__device__ __align__(256) float  g_off[NOFF*NVOX];  // offsets, transposed [j][v]
__device__ __align__(256) float  g_mask[NMSK*NVOX]; // mask logits, transposed [j][v]
__device__ __align__(256) float  g_samp[NC*NVOX];   // sampled+masked result, c-major [c][v]
__device__ float g_part[KDW_BLOCKS*2];
__device__ float g_stats[2];
__device__ __align__(256) float g_wtT[NC*NJP];      // weights [k][j], j-reordered+padded
__device__ float g_bias[NJP];

// ---------------------------------------------------------------------------
// Kernel 0: build reordered weight matrix [k][j] + bias
// ---------------------------------------------------------------------------
__global__ void k_init(const float* __restrict__ inp_w, const float* __restrict__ off_w,
                       const float* __restrict__ mask_w,
                       const float* __restrict__ inp_b, const float* __restrict__ off_b,
                       const float* __restrict__ mask_b) {
    int gid = blockIdx.x * 256 + threadIdx.x;
    if (gid < NC * NJP) {
        int k = gid / NJP, j = gid - k * NJP;
        float v = 0.f;
        if (j < 64)       v = inp_w[k * NC + j];
        else if (j < 226) v = off_w[k * NOFF + (j - 64)];
        else if (j < 280) v = mask_w[k * NMSK + (j - 226)];
        g_wtT[gid] = v;
    }
    if (gid < NJP) {
        int j = gid;
        float b = 0.f;
        if (j < 64)       b = inp_b[j];
        else if (j < 226) b = off_b[j - 64];
        else if (j < 280) b = mask_b[j - 226];
        g_bias[j] = b;
    }
}

// ---------------------------------------------------------------------------
// Kernel 1: depthwise 3x3x3 conv via smem slab (3 z-slices + halo).
// ---------------------------------------------------------------------------
__global__ void k_dw(const float* __restrict__ x, const float* __restrict__ dw_w) {
    int bz = blockIdx.x, c = blockIdx.y;
    int tid = threadIdx.x;
    __shared__ float s[3][34][34];
    __shared__ float sh[8][2];

    const float* xs = x + c * NVOX;
    for (int i = tid; i < 3 * 34 * 34; i += 256) {
        int sl = i / 1156;
        int rem = i - sl * 1156;
        int yy = rem / 34;
        int xx = rem - yy * 34;
        int z = bz + sl - 1, y = yy - 1, xg = xx - 1;
        float val = 0.f;
        if ((unsigned)z < 32u && (unsigned)y < 32u && (unsigned)xg < 32u)
            val = xs[(z << 10) + (y << 5) + xg];
        s[sl][yy][xx] = val;
    }
    float w[27];
#pragma unroll
    for (int k = 0; k < 27; k++) w[k] = __ldg(dw_w + c * 27 + k);
    __syncthreads();

    float ls = 0.f, ls2 = 0.f;
#pragma unroll
    for (int q = 0; q < 4; q++) {
        int vloc = q * 256 + tid;
        int iy = vloc >> 5, ix = vloc & 31;
        float acc = 0.f;
#pragma unroll
        for (int kz = 0; kz < 3; kz++)
#pragma unroll
            for (int ky = 0; ky < 3; ky++)
#pragma unroll
                for (int kx = 0; kx < 3; kx++)
                    acc = fmaf(w[kz*9 + ky*3 + kx], s[kz][iy + ky][ix + kx], acc);
        g_xc[c * NVOX + (bz << 10) + vloc] = acc;
        ls += acc; ls2 += acc * acc;
    }

#pragma unroll
    for (int o = 16; o > 0; o >>= 1) {
        ls  += __shfl_down_sync(0xffffffffu, ls,  o);
        ls2 += __shfl_down_sync(0xffffffffu, ls2, o);
    }
    int lane = tid & 31, warp = tid >> 5;
    if (lane == 0) { sh[warp][0] = ls; sh[warp][1] = ls2; }
    __syncthreads();
    if (tid == 0) {
        float S = 0.f, S2 = 0.f;
#pragma unroll
        for (int i = 0; i < 8; i++) { S += sh[i][0]; S2 += sh[i][1]; }
        int bid = c * 32 + bz;
        g_part[bid * 2]     = S;
        g_part[bid * 2 + 1] = S2;
    }
}

// ---------------------------------------------------------------------------
// Kernel 2: finalize mean / rstd
// ---------------------------------------------------------------------------
__global__ void k_stats() {
    int tid = threadIdx.x;
    float s = 0.f, s2 = 0.f;
    for (int i = tid; i < KDW_BLOCKS; i += 1024) {
        float2 p = reinterpret_cast<const float2*>(g_part)[i];
        s += p.x; s2 += p.y;
    }
#pragma unroll
    for (int o = 16; o > 0; o >>= 1) {
        s  += __shfl_down_sync(0xffffffffu, s,  o);
        s2 += __shfl_down_sync(0xffffffffu, s2, o);
    }
    __shared__ float sh[32][2];
    int lane = tid & 31, wid = tid >> 5;
    if (lane == 0) { sh[wid][0] = s; sh[wid][1] = s2; }
    __syncthreads();
    if (tid == 0) {
        float S = 0.f, S2 = 0.f;
#pragma unroll
        for (int i = 0; i < 32; i++) { S += sh[i][0]; S2 += sh[i][1]; }
        float n   = (float)(NVOX * NC);
        float mu  = S / n;
        float var = S2 / n - mu * mu;
        g_stats[0] = mu;
        g_stats[1] = rsqrtf(var + 1e-5f);
    }
}

// ---------------------------------------------------------------------------
// Kernel 3: tiled GEMM. C[v][j] = A[v][k] * W[k][j], M=32768, N=320, K=64.
// jt==0 epilogue writes fp16 into the ring-padded volume.
// ---------------------------------------------------------------------------
__global__ void __launch_bounds__(256)
k_point(const float* __restrict__ x,
        const float* __restrict__ gn_w, const float* __restrict__ gn_b) {
    int jt = blockIdx.y;
    int vbase = blockIdx.x * 128;
    int tid = threadIdx.x;
    __shared__ float sA[64 * 128];
    __shared__ float sB[64 * 64];

#pragma unroll
    for (int i = 0; i < 4; i++) {
        int lin = i * 1024 + tid * 4;
        int k = lin >> 6, j = lin & 63;
        *reinterpret_cast<float4*>(&sB[lin]) =
            *reinterpret_cast<const float4*>(&g_wtT[k * NJP + jt * 64 + j]);
    }
    if (jt == 0) {
#pragma unroll
        for (int i = 0; i < 8; i++) {
            int lin = i * 1024 + tid * 4;
            int k = lin >> 7, vl = lin & 127;
            *reinterpret_cast<float4*>(&sA[lin]) =
                *reinterpret_cast<const float4*>(&x[k * NVOX + vbase + vl]);
        }
    } else {
        float mu = g_stats[0], rstd = g_stats[1];
#pragma unroll
        for (int i = 0; i < 8; i++) {
            int lin = i * 1024 + tid * 4;
            int k = lin >> 7, vl = lin & 127;
            float gw = __ldg(gn_w + k) * rstd;
            float gb = __ldg(gn_b + k) - mu * gw;
            float4 xv = *reinterpret_cast<const float4*>(&g_xc[k * NVOX + vbase + vl]);
            float r[4] = {xv.x, xv.y, xv.z, xv.w};
#pragma unroll
            for (int e = 0; e < 4; e++) {
                float xn = r[e] * gw + gb;
                float u = xn + 0.044715f * xn * xn * xn;
                r[e] = xn / (1.f + __expf(-1.5957691216057308f * u));
            }
            *reinterpret_cast<float4*>(&sA[lin]) = make_float4(r[0], r[1], r[2], r[3]);
        }
    }
    __syncthreads();

    int tx = tid & 15, ty = tid >> 4;
    float acc[8][4];
#pragma unroll
    for (int i = 0; i < 8; i++)
#pragma unroll
        for (int j = 0; j < 4; j++) acc[i][j] = 0.f;

    const float4* A4 = reinterpret_cast<const float4*>(sA);
    const float4* B4 = reinterpret_cast<const float4*>(sB);
#pragma unroll 8
    for (int k = 0; k < 64; k++) {
        float4 a0 = A4[k * 32 + tx];
        float4 a1 = A4[k * 32 + 16 + tx];
        float4 b  = B4[k * 16 + ty];
        float av[8] = {a0.x, a0.y, a0.z, a0.w, a1.x, a1.y, a1.z, a1.w};
        float bv[4] = {b.x, b.y, b.z, b.w};
#pragma unroll
        for (int i = 0; i < 8; i++)
#pragma unroll
            for (int j = 0; j < 4; j++)
                acc[i][j] = fmaf(av[i], bv[j], acc[i][j]);
    }

    if (jt == 0) {
        int o = ty * 4;
        int g = o >> 5, ch = o & 31;
        float4 b4 = *reinterpret_cast<const float4*>(&g_bias[o]);
#pragma unroll
        for (int vi = 0; vi < 8; vi++) {
            int v = vbase + ((vi & 4) << 4) + tx * 4 + (vi & 3);
            int iz = v >> 10, iy = (v >> 5) & 31, ix = v & 31;
            int pos = (((g * DP2 + iz + 2) * DP2 + iy + 2) * DP2 + ix + 2);
            __half2 h01 = __floats2half2_rn(acc[vi][0] + b4.x, acc[vi][1] + b4.y);
            __half2 h23 = __floats2half2_rn(acc[vi][2] + b4.z, acc[vi][3] + b4.w);
            uint2 u;
            u.x = *reinterpret_cast<unsigned*>(&h01);
            u.y = *reinterpret_cast<unsigned*>(&h23);
            *reinterpret_cast<uint2*>(&g_xph[(pos << 5) + ch]) = u;
        }
    } else {
#pragma unroll
        for (int jj = 0; jj < 4; jj++) {
            int j = jt * 64 + ty * 4 + jj;
            float* dst;
            if (j < 226)      dst = g_off  + (j - 64)  * NVOX;
            else if (j < 280) dst = g_mask + (j - 226) * NVOX;
            else continue;
            float bj = g_bias[j];
            *reinterpret_cast<float4*>(dst + vbase + tx * 4) =
                make_float4(acc[0][jj] + bj, acc[1][jj] + bj,
                            acc[2][jj] + bj, acc[3][jj] + bj);
            *reinterpret_cast<float4*>(dst + vbase + 64 + tx * 4) =
                make_float4(acc[4][jj] + bj, acc[5][jj] + bj,
                            acc[6][jj] + bj, acc[7][jj] + bj);
        }
    }
}

// ---------------------------------------------------------------------------
// Kernel 4: deformable trilinear sampling (fp16 volume) + masked accumulate.
// Block = 4x4x4 voxel cube x ONE group; 256 threads = 64 vox x 4 ch-lanes
// (8 fp16 channels per lane via one float4 load per tap). Result -> g_samp.
// ---------------------------------------------------------------------------
__global__ void __launch_bounds__(256) k_samp() {
    int bid = blockIdx.x;            // 1024 = 512 tiles x 2 groups
    int gi = bid & 1;
    int tile = bid >> 1;
    int tbx = tile & 7, tby = (tile >> 3) & 7, tbz = tile >> 6;
    int tid = threadIdx.x;

    __shared__ float s_off[64][81];
    __shared__ float s_m[64][28];

    // stage this group's offsets (81 rows) and mask logits (27 rows)
    for (int idx = tid; idx < 64 * 81; idx += 256) {
        int j = idx >> 6, vl = idx & 63;
        int vx = tbx * 4 + (vl & 3), vy = tby * 4 + ((vl >> 2) & 3), vz = tbz * 4 + (vl >> 4);
        s_off[vl][j] = g_off[(gi * 81 + j) * NVOX + (vz << 10) + (vy << 5) + vx];
    }
    for (int idx = tid; idx < 64 * 27; idx += 256) {
        int j = idx >> 6, vl = idx & 63;
        int vx = tbx * 4 + (vl & 3), vy = tby * 4 + ((vl >> 2) & 3), vz = tbz * 4 + (vl >> 4);
        s_m[vl][j] = g_mask[(gi * 27 + j) * NVOX + (vz << 10) + (vy << 5) + vx];
    }
    __syncthreads();

    // softmax over 27 points, one thread per voxel
    if (tid < 64) {
        float* m = s_m[tid];
        float mx = -1e30f;
#pragma unroll
        for (int p = 0; p < NP; p++) mx = fmaxf(mx, m[p]);
        float s = 0.f;
#pragma unroll
        for (int p = 0; p < NP; p++) { float e = __expf(m[p] - mx); m[p] = e; s += e; }
        float inv = 1.f / s;
#pragma unroll
        for (int p = 0; p < NP; p++) m[p] *= inv;
    }
    __syncthreads();

    int c8 = tid & 3;                // 8 channels per lane
    int vv = tid >> 2;               // local voxel 0..63
    int ix = tbx * 4 + (vv & 3);
    int iy = tby * 4 + ((vv >> 2) & 3);
    int iz = tbz * 4 + (vv >> 4);

    const float4* vol4 = reinterpret_cast<const float4*>(g_xph) + gi * HVOL4 + c8;
    const float* offp = s_off[vv];
    const float* mp   = s_m[vv];

    float acc[8];
#pragma unroll
    for (int e = 0; e < 8; e++) acc[e] = 0.f;

    int kx = 0, ky = 0, kz = 0;
#pragma unroll 1
    for (int p = 0; p < NP; p++) {
        float ox = offp[p * 3 + 0];
        float oy = offp[p * 3 + 1];
        float oz = offp[p * 3 + 2];
        float sx = (float)(ix + kx + 1) + 0.25f * ox;
        float sy = (float)(iy + ky + 1) + 0.5f  * oy;
        float sz = (float)(iz + kz + 1) + 0.5f  * oz;
        if (++kx == 3) { kx = 0; if (++ky == 3) { ky = 0; ++kz; } }

        float xf = floorf(sx), yf = floorf(sy), zf = floorf(sz);
        float fx = sx - xf, fy = sy - yf, fz = sz - zf;
        int x0 = (int)xf, y0 = (int)yf, z0 = (int)zf;
        int x0c = min(max(x0, 0), DP2 - 1),     y0c = min(max(y0, 0), DP2 - 1);
        int z0c = min(max(z0, 0), DP2 - 1);
        int x1c = min(max(x0 + 1, 0), DP2 - 1), y1c = min(max(y0 + 1, 0), DP2 - 1);
        int z1c = min(max(z0 + 1, 0), DP2 - 1);

        int zy00 = (z0c * DP2 + y0c) * DP2;
        int zy01 = (z0c * DP2 + y1c) * DP2;
        int zy10 = (z1c * DP2 + y0c) * DP2;
        int zy11 = (z1c * DP2 + y1c) * DP2;

        float4 t000 = vol4[(zy00 + x0c) << 2];
        float4 t001 = vol4[(zy00 + x1c) << 2];
        float4 t010 = vol4[(zy01 + x0c) << 2];
        float4 t011 = vol4[(zy01 + x1c) << 2];
        float4 t100 = vol4[(zy10 + x0c) << 2];
        float4 t101 = vol4[(zy10 + x1c) << 2];
        float4 t110 = vol4[(zy11 + x0c) << 2];
        float4 t111 = vol4[(zy11 + x1c) << 2];

        float m = mp[p];
        float gx1 = fx, gx0 = 1.f - fx;
        float gy1 = fy, gy0 = 1.f - fy;
        float gz1 = fz, gz0 = 1.f - fz;
        float w00 = gz0 * gy0 * m, w01 = gz0 * gy1 * m;
        float w10 = gz1 * gy0 * m, w11 = gz1 * gy1 * m;
        float w000 = w00 * gx0, w001 = w00 * gx1;
        float w010 = w01 * gx0, w011 = w01 * gx1;
        float w100 = w10 * gx0, w101 = w10 * gx1;
        float w110 = w11 * gx0, w111 = w11 * gx1;

#define TAP(T, W) { \
        const __half2* hh = reinterpret_cast<const __half2*>(&T); \
        float2 f0 = __half22float2(hh[0]); \
        float2 f1 = __half22float2(hh[1]); \
        float2 f2 = __half22float2(hh[2]); \
        float2 f3 = __half22float2(hh[3]); \
        acc[0] = fmaf(W, f0.x, acc[0]); acc[1] = fmaf(W, f0.y, acc[1]); \
        acc[2] = fmaf(W, f1.x, acc[2]); acc[3] = fmaf(W, f1.y, acc[3]); \
        acc[4] = fmaf(W, f2.x, acc[4]); acc[5] = fmaf(W, f2.y, acc[5]); \
        acc[6] = fmaf(W, f3.x, acc[6]); acc[7] = fmaf(W, f3.y, acc[7]); }
        TAP(t000, w000) TAP(t001, w001) TAP(t010, w010) TAP(t011, w011)
        TAP(t100, w100) TAP(t101, w101) TAP(t110, w110) TAP(t111, w111)
#undef TAP
    }

    // write sampled result, c-major [c][v]
    int v = (iz << 10) + (iy << 5) + ix;
    int cbase = gi * GC + c8 * 8;
#pragma unroll
    for (int e = 0; e < 8; e++)
        g_samp[(cbase + e) * NVOX + v] = acc[e];
}

// ---------------------------------------------------------------------------
// Kernel 5: output GEMM. out[v][oc] = g_samp[c][v]^T @ out_w[c][oc] + out_b.
// ---------------------------------------------------------------------------
__global__ void __launch_bounds__(256)
k_out(const float* __restrict__ out_w, const float* __restrict__ out_b,
      float* __restrict__ out) {
    int vbase = blockIdx.x * 128;
    int tid = threadIdx.x;
    __shared__ float sA[64 * 128];
    __shared__ float sB[64 * 64];

#pragma unroll
    for (int i = 0; i < 4; i++) {
        int lin = i * 1024 + tid * 4;
        *reinterpret_cast<float4*>(&sB[lin]) =
            *reinterpret_cast<const float4*>(&out_w[lin]);
    }
#pragma unroll
    for (int i = 0; i < 8; i++) {
        int lin = i * 1024 + tid * 4;
        int k = lin >> 7, vl = lin & 127;
        *reinterpret_cast<float4*>(&sA[lin]) =
            *reinterpret_cast<const float4*>(&g_samp[k * NVOX + vbase + vl]);
    }
    __syncthreads();

    int tx = tid & 15, ty = tid >> 4;
    float acc[8][4];
#pragma unroll
    for (int i = 0; i < 8; i++)
#pragma unroll
        for (int j = 0; j < 4; j++) acc[i][j] = 0.f;

    const float4* A4 = reinterpret_cast<const float4*>(sA);
    const float4* B4 = reinterpret_cast<const float4*>(sB);
#pragma unroll 8
    for (int k = 0; k < 64; k++) {
        float4 a0 = A4[k * 32 + tx];
        float4 a1 = A4[k * 32 + 16 + tx];
        float4 b  = B4[k * 16 + ty];
        float av[8] = {a0.x, a0.y, a0.z, a0.w, a1.x, a1.y, a1.z, a1.w};
        float bv[4] = {b.x, b.y, b.z, b.w};
#pragma unroll
        for (int i = 0; i < 8; i++)
#pragma unroll
            for (int j = 0; j < 4; j++)
                acc[i][j] = fmaf(av[i], bv[j], acc[i][j]);
    }

    float4 b4 = *reinterpret_cast<const float4*>(&out_b[ty * 4]);
#pragma unroll
    for (int vi = 0; vi < 8; vi++) {
        int v = vbase + ((vi & 4) << 4) + tx * 4 + (vi & 3);
        *reinterpret_cast<float4*>(&out[v * NC + ty * 4]) =
            make_float4(acc[vi][0] + b4.x, acc[vi][1] + b4.y,
                        acc[vi][2] + b4.z, acc[vi][3] + b4.w);
    }
}

// ---------------------------------------------------------------------------
extern "C" void kernel_launch(void* const* d_in, const int* in_sizes, int n_in,
                              void* d_out, int out_size) {
    const float* x      = (const float*)d_in[0];
    const float* dw_w   = (const float*)d_in[1];
    const float* gn_w   = (const float*)d_in[2];
    const float* gn_b   = (const float*)d_in[3];
    const float* inp_w  = (const float*)d_in[4];
    const float* inp_b  = (const float*)d_in[5];
    const float* off_w  = (const float*)d_in[6];
    const float* off_b  = (const float*)d_in[7];
    const float* mask_w = (const float*)d_in[8];
    const float* mask_b = (const float*)d_in[9];
    const float* out_w  = (const float*)d_in[10];
    const float* out_b  = (const float*)d_in[11];
    float* out = (float*)d_out;

    k_init<<<(NC * NJP + 255) / 256, 256>>>(inp_w, off_w, mask_w, inp_b, off_b, mask_b);
    k_dw<<<dim3(32, 64), 256>>>(x, dw_w);
    k_stats<<<1, 1024>>>();
    k_point<<<dim3(NVOX / 128, 5), 256>>>(x, gn_w, gn_b);
    k_samp<<<1024, 256>>>();
    k_out<<<NVOX / 128, 256>>>(out_w, out_b, out);
}